// round 16
// baseline (speedup 1.0000x reference)
#include <cuda_runtime.h>
#include <math.h>

#define NC 64
#define NF 128
#define NS 192
#define RPB 8        // rays per block, 1 warp each
#define FULLM 0xffffffffu

// compare-exchange a pair of registers; 'up' => a gets min
#define CEPAIR(a, b, up) { float _mn = fminf(a, b), _mx = fmaxf(a, b); \
                           a = (up) ? _mn : _mx; b = (up) ? _mx : _mn; }

__global__ __launch_bounds__(256, 5) void gridnerf_kernel(
    const float* __restrict__ ro,      // [N,3]
    const float* __restrict__ rd,      // [N,3]
    const float* __restrict__ cw,      // [N,NC]
    const float* __restrict__ ct,      // [N,NC]
    const float* __restrict__ uu_in,   // [N,NF]
    const float* __restrict__ colors,  // [N,NS,3]
    const float* __restrict__ dens,    // [N,NS]
    float* __restrict__ out_rgb,       // [N,3]
    float* __restrict__ out_depth,     // [N]
    float* __restrict__ out_op,        // [N]
    float* __restrict__ out_fp,        // [N,NS,3]
    int nrays)
{
    const int L   = threadIdx.x & 31;
    const int w   = threadIdx.x >> 5;
    const int ray = blockIdx.x * RPB + w;
    if (ray >= nrays) return;          // warp-uniform exit; no block barriers used

    __shared__ float2 sh_cc[RPB][64];   // (cdf[i], ct[i])
    __shared__ float  sh_t [RPB][192];  // merged sorted t
    __shared__ float2 sh_tw[RPB][192];  // (t, weight)

    float2* cc  = sh_cc[w];
    float*  st  = sh_t[w];
    float2* stw = sh_tw[w];

    // ---- A: global loads (coalesced / vectorized) ----
    const float4 u4 = ((const float4*)(uu_in + (size_t)ray * NF))[L];
    float v0 = u4.x, v1 = u4.y, v2 = u4.z, v3 = u4.w;   // elements 4L..4L+3

    const float2 cw2 = ((const float2*)(cw + (size_t)ray * NC))[L];
    const float2 ct2 = ((const float2*)(ct + (size_t)ray * NC))[L];

    const float ox = ro[3 * ray + 0], oy = ro[3 * ray + 1], oz = ro[3 * ray + 2];
    const float dx = rd[3 * ray + 0], dy = rd[3 * ray + 1], dz = rd[3 * ray + 2];
    const float dnorm = sqrtf(dx * dx + dy * dy + dz * dz);

    // ---- B: cdf build (pair-per-lane warp scan); boundaries stay in regs ----
    float cdf_b1, cdf_b2;               // cdf[2L+1], cdf[2L+2]
    {
        const float a  = cw2.x + 1e-5f;
        const float b  = cw2.y + 1e-5f;
        const float ps = a + b;
        float inc = ps;
        #pragma unroll
        for (int off = 1; off < 32; off <<= 1) {
            float n = __shfl_up_sync(FULLM, inc, off);
            if (L >= off) inc += n;
        }
        const float total = __shfl_sync(FULLM, inc, 31);
        const float invt  = 1.f / total;
        const float excl  = inc - ps;
        const float cdf_e = excl * invt;          // cdf[2L]
        cdf_b1 = (excl + a)  * invt;              // cdf[2L+1]
        cdf_b2 = (excl + ps) * invt;              // cdf[2L+2]
        *(float4*)(cc + 2 * L) = make_float4(cdf_e, ct2.x, cdf_b1, ct2.y);
    }

    // ---- C: bitonic sort of 128 u, 4 elements/thread (e = 4L+i) ----
    #pragma unroll
    for (int k = 2; k <= 128; k <<= 1) {
        #pragma unroll
        for (int j = k >> 1; j >= 4; j >>= 1) {
            const bool up = ((L & (k >> 2)) == 0);   // k>=8 here
            const bool lw = ((L & (j >> 2)) == 0);
            const bool km = (up == lw);
            float w0 = __shfl_xor_sync(FULLM, v0, j >> 2);
            float w1 = __shfl_xor_sync(FULLM, v1, j >> 2);
            float w2 = __shfl_xor_sync(FULLM, v2, j >> 2);
            float w3 = __shfl_xor_sync(FULLM, v3, j >> 2);
            v0 = km ? fminf(v0, w0) : fmaxf(v0, w0);
            v1 = km ? fminf(v1, w1) : fmaxf(v1, w1);
            v2 = km ? fminf(v2, w2) : fmaxf(v2, w2);
            v3 = km ? fminf(v3, w3) : fmaxf(v3, w3);
        }
        if (k >= 4) {  // j = 2 : pairs (v0,v2), (v1,v3)
            const bool up = (k == 4) ? ((L & 1) == 0) : ((L & (k >> 2)) == 0);
            CEPAIR(v0, v2, up); CEPAIR(v1, v3, up);
        }
        // j = 1 : pairs (v0,v1), (v2,v3)
        if (k == 2) {
            CEPAIR(v0, v1, true);  CEPAIR(v2, v3, false);
        } else {
            const bool up = (k == 4) ? ((L & 1) == 0) : ((L & (k >> 2)) == 0);
            CEPAIR(v0, v1, up);    CEPAIR(v2, v3, up);
        }
    }
    __syncwarp();

    // ---- D1: boundary ranks via REGISTER search; coarse scatter ----
    int s1, s2;   // ranks of cdf[2L+1], cdf[2L+2] in sorted u (non-decreasing seq)
    {
        const float m = v3;  // lane max of sorted quad; ascending across lanes
        auto rank128r = [&](float c) -> int {
            float pv; int r = 0;
            pv = __shfl_sync(FULLM, m, 15);     if (pv < c) r = 16;
            pv = __shfl_sync(FULLM, m, r + 7);  if (pv < c) r += 8;
            pv = __shfl_sync(FULLM, m, r + 3);  if (pv < c) r += 4;
            pv = __shfl_sync(FULLM, m, r + 1);  if (pv < c) r += 2;
            pv = __shfl_sync(FULLM, m, r);      if (pv < c) r += 1;
            pv = __shfl_sync(FULLM, m, 31);     if (r == 31 && pv < c) r = 32;
            const int rl = (r < 32) ? r : 31;
            const float a0 = __shfl_sync(FULLM, v0, rl);
            const float a1 = __shfl_sync(FULLM, v1, rl);
            const float a2 = __shfl_sync(FULLM, v2, rl);
            int rank = 4 * r;                   // r==32 -> 128
            if (r < 32) rank += (a0 < c) + (a1 < c) + (a2 < c);
            return rank;
        };
        s1 = rank128r(cdf_b1);
        s2 = rank128r(cdf_b2);
        int r0 = __shfl_up_sync(FULLM, s2, 1);
        if (L == 0) r0 = 0;
        st[2 * L + r0]     = ct2.x;
        st[2 * L + 1 + s1] = ct2.y;
    }

    // ---- D2: lo via register search over the sorted boundary ranks
    //      (S = [s1(0),s2(0),s1(1),s2(1),...] is non-decreasing; no atomics,
    //       no histogram). cnt(e) = #{S_j <= e}; lo = 1 + cnt. ----
    {
        auto cnt_le = [&](int e) -> int {
            int pv, r = 0;
            pv = __shfl_sync(FULLM, s2, 15);     if (pv <= e) r = 16;
            pv = __shfl_sync(FULLM, s2, r + 7);  if (pv <= e) r += 8;
            pv = __shfl_sync(FULLM, s2, r + 3);  if (pv <= e) r += 4;
            pv = __shfl_sync(FULLM, s2, r + 1);  if (pv <= e) r += 2;
            pv = __shfl_sync(FULLM, s2, r);      if (pv <= e) r += 1;
            pv = __shfl_sync(FULLM, s2, 31);     if (r == 31 && pv <= e) r = 32;
            const int rl = (r < 32) ? r : 31;
            const int s1r = __shfl_sync(FULLM, s1, rl);
            return (r == 32) ? 64 : (2 * r + (s1r <= e));
        };
        const float va[4] = {v0, v1, v2, v3};
        #pragma unroll
        for (int i = 0; i < 4; i++) {
            const int   e  = 4 * L + i;
            const int   lo = 1 + cnt_le(e);
            const float uu = va[i];
            const int below = min(lo - 1, NC - 1);
            const int above = min(lo,     NC - 1);
            const float2 ccb = cc[below];
            const float2 cca = cc[above];
            float denom = cca.x - ccb.x;
            if (denom < 1e-5f) denom = 1.f;
            const float tt = (uu - ccb.x) / denom;
            const float fv = ccb.y + tt * (cca.y - ccb.y);
            st[e + min(lo, NC)] = fv;
        }
    }
    __syncwarp();

    // ---- F: alpha + transmittance (thread owns samples 6L..6L+5) ----
    float dep = 0.f, op = 0.f;
    {
        const float2 tA = *(const float2*)(st + 6 * L);
        const float2 tB = *(const float2*)(st + 6 * L + 2);
        const float2 tC = *(const float2*)(st + 6 * L + 4);
        const float tb[6] = {tA.x, tA.y, tB.x, tB.y, tC.x, tC.y};
        // st[6L+6] == next lane's tA.x (lane 31's value unused: 1e10 branch)
        const float t6 = __shfl_down_sync(FULLM, tA.x, 1);

        const float* dvp = dens + (size_t)ray * NS + 6 * L;
        const float2 dva = *(const float2*)(dvp + 0);
        const float2 dvb = *(const float2*)(dvp + 2);
        const float2 dvc = *(const float2*)(dvp + 4);
        const float dvv[6] = {dva.x, dva.y, dvb.x, dvb.y, dvc.x, dvc.y};

        float alpha[6];
        float run = 1.f;
        #pragma unroll
        for (int i = 0; i < 6; i++) {
            float dist;
            if (i < 5)          dist = tb[i + 1] - tb[i];
            else if (L == 31)   dist = 1e10f;
            else                dist = t6 - tb[5];
            dist *= dnorm;
            alpha[i] = 1.f - __expf(-dvv[i] * dist);
            run *= (1.f - alpha[i] + 1e-10f);
        }
        float inc = run;
        #pragma unroll
        for (int off = 1; off < 32; off <<= 1) {
            float n = __shfl_up_sync(FULLM, inc, off);
            if (L >= off) inc *= n;
        }
        float wex = __shfl_up_sync(FULLM, inc, 1);
        if (L == 0) wex = 1.f;

        float run2 = wex;                 // running transmittance
        #pragma unroll
        for (int i = 0; i < 6; i++) {
            const float wt = alpha[i] * run2;
            stw[6 * L + i] = make_float2(tb[i], wt);
            dep += wt * tb[i];
            op  += wt;
            run2 *= (1.f - alpha[i] + 1e-10f);
        }
    }
    __syncwarp();

    // ---- G: float4 fp stores + rgb accumulation (contiguous stw reads) ----
    float A0 = 0.f, A1 = 0.f, A2 = 0.f;
    const int rB = L % 3;
    {
        const float oR0 = (rB == 0) ? ox : ((rB == 1) ? oy : oz);
        const float oR1 = (rB == 0) ? oy : ((rB == 1) ? oz : ox);
        const float oR2 = (rB == 0) ? oz : ((rB == 1) ? ox : oy);
        const float dR0 = (rB == 0) ? dx : ((rB == 1) ? dy : dz);
        const float dR1 = (rB == 0) ? dy : ((rB == 1) ? dz : dx);
        const float dR2 = (rB == 0) ? dz : ((rB == 1) ? dx : dy);
        float* fpb = out_fp + (size_t)ray * (NS * 3);
        const float4* c4 = (const float4*)(colors + (size_t)ray * (NS * 3));

        #pragma unroll
        for (int h = 0; h < 4; h++) {
            const float4 cvi = __ldg(&c4[32 * h + L]);
            const int e0  = 128 * h + 4 * L;
            const int sa  = e0 / 3;
            const int r0  = e0 - 3 * sa;           // e0 % 3
            const float2 twa = stw[sa];
            const float2 twb = stw[sa + 1];
            // float j uses sample sa+1 iff r0 + j >= 3
            const float t0 = twa.x;
            const float w0 = twa.y;
            const float t1 = (r0 == 2) ? twb.x : twa.x;
            const float w1 = (r0 == 2) ? twb.y : twa.y;
            const float t2 = (r0 >= 1) ? twb.x : twa.x;
            const float w2 = (r0 >= 1) ? twb.y : twa.y;
            const float t3 = twb.x;
            const float w3 = twb.y;
            // channel slot q_j = (2h + j) % 3 (compile-time)
            const int q0 = (2 * h + 0) % 3, q1 = (2 * h + 1) % 3;
            const int q2 = (2 * h + 2) % 3, q3 = (2 * h + 3) % 3;
            const float oA = (q0 == 0) ? oR0 : ((q0 == 1) ? oR1 : oR2);
            const float dA = (q0 == 0) ? dR0 : ((q0 == 1) ? dR1 : dR2);
            const float oB = (q1 == 0) ? oR0 : ((q1 == 1) ? oR1 : oR2);
            const float dB = (q1 == 0) ? dR0 : ((q1 == 1) ? dR1 : dR2);
            const float oC = (q2 == 0) ? oR0 : ((q2 == 1) ? oR1 : oR2);
            const float dC = (q2 == 0) ? dR0 : ((q2 == 1) ? dR1 : dR2);
            const float oD = (q3 == 0) ? oR0 : ((q3 == 1) ? oR1 : oR2);
            const float dD = (q3 == 0) ? dR0 : ((q3 == 1) ? dR1 : dR2);
            *(float4*)(fpb + e0) = make_float4(oA + dA * t0, oB + dB * t1,
                                               oC + dC * t2, oD + dD * t3);
            const float g0 = w0 * cvi.x, g1 = w1 * cvi.y;
            const float g2 = w2 * cvi.z, g3 = w3 * cvi.w;
            if (q0 == 0) A0 += g0; else if (q0 == 1) A1 += g0; else A2 += g0;
            if (q1 == 0) A0 += g1; else if (q1 == 1) A1 += g1; else A2 += g1;
            if (q2 == 0) A0 += g2; else if (q2 == 1) A1 += g2; else A2 += g2;
            if (q3 == 0) A0 += g3; else if (q3 == 1) A1 += g3; else A2 += g3;
        }

        // tail: elements 512 + 2L, 512 + 2L + 1 (float2)
        {
            const float2* c2p = (const float2*)(colors + (size_t)ray * (NS * 3) + 512);
            const float2 cvi = __ldg(&c2p[L]);
            const int e0 = 512 + 2 * L;
            const int s0 = e0 / 3;
            const int s1t = (e0 + 1) / 3;
            const float2 tw0 = stw[s0];
            const float2 tw1 = stw[s1t];
            const int qt0 = (2 + rB) % 3;
            const int qt1 = rB;
            const float o0 = (qt0 == 0) ? oR0 : ((qt0 == 1) ? oR1 : oR2);
            const float d0 = (qt0 == 0) ? dR0 : ((qt0 == 1) ? dR1 : dR2);
            const float o1 = (qt1 == 0) ? oR0 : ((qt1 == 1) ? oR1 : oR2);
            const float d1 = (qt1 == 0) ? dR0 : ((qt1 == 1) ? dR1 : dR2);
            *(float2*)(fpb + e0) = make_float2(o0 + d0 * tw0.x, o1 + d1 * tw1.x);
            const float g0 = tw0.y * cvi.x;
            const float g1 = tw1.y * cvi.y;
            if (qt0 == 0) A0 += g0; else if (qt0 == 1) A1 += g0; else A2 += g0;
            if (qt1 == 0) A0 += g1; else if (qt1 == 1) A1 += g1; else A2 += g1;
        }
    }

    // ---- H: final reductions (single warp, no shared) ----
    {
        // channel c lives in A[(c - rB) mod 3] == A[(c + 2L) % 3]
        const int i0 = (2 * L) % 3, i1 = (2 * L + 1) % 3, i2 = (2 * L + 2) % 3;
        float rC = (i0 == 0) ? A0 : ((i0 == 1) ? A1 : A2);
        float gC = (i1 == 0) ? A0 : ((i1 == 1) ? A1 : A2);
        float bC = (i2 == 0) ? A0 : ((i2 == 1) ? A1 : A2);
        #pragma unroll
        for (int off = 16; off; off >>= 1) {
            rC  += __shfl_xor_sync(FULLM, rC,  off);
            gC  += __shfl_xor_sync(FULLM, gC,  off);
            bC  += __shfl_xor_sync(FULLM, bC,  off);
            dep += __shfl_xor_sync(FULLM, dep, off);
            op  += __shfl_xor_sync(FULLM, op,  off);
        }
        if (L == 0) {
            out_rgb[3 * ray + 0] = rC;
            out_rgb[3 * ray + 1] = gC;
            out_rgb[3 * ray + 2] = bC;
            out_depth[ray] = dep;
            out_op[ray]    = op;
        }
    }
}

extern "C" void kernel_launch(void* const* d_in, const int* in_sizes, int n_in,
                              void* d_out, int out_size)
{
    const float* ro     = (const float*)d_in[0];
    const float* rd     = (const float*)d_in[1];
    const float* cw     = (const float*)d_in[2];
    const float* ct     = (const float*)d_in[3];
    const float* u      = (const float*)d_in[4];
    const float* colors = (const float*)d_in[5];
    const float* dens   = (const float*)d_in[6];

    const int N = in_sizes[0] / 3;

    float* out       = (float*)d_out;
    float* out_rgb   = out;                 // [N,3]
    float* out_depth = out + (size_t)N * 3; // [N]
    float* out_op    = out_depth + N;       // [N]
    float* out_fp    = out_op + N;          // [N,NS,3]

    const int blocks = (N + RPB - 1) / RPB;
    gridnerf_kernel<<<blocks, 32 * RPB>>>(ro, rd, cw, ct, u, colors, dens,
                                          out_rgb, out_depth, out_op, out_fp, N);
}

// round 17
// speedup vs baseline: 1.0740x; 1.0740x over previous
#include <cuda_runtime.h>
#include <math.h>

#define NC 64
#define NF 128
#define NS 192
#define RPB 8        // rays per block, 1 warp each
#define FULLM 0xffffffffu

// compare-exchange a pair of registers; 'up' => a gets min
#define CEPAIR(a, b, up) { float _mn = fminf(a, b), _mx = fmaxf(a, b); \
                           a = (up) ? _mn : _mx; b = (up) ? _mx : _mn; }

__global__ __launch_bounds__(256, 6) void gridnerf_kernel(
    const float* __restrict__ ro,      // [N,3]
    const float* __restrict__ rd,      // [N,3]
    const float* __restrict__ cw,      // [N,NC]
    const float* __restrict__ ct,      // [N,NC]
    const float* __restrict__ uu_in,   // [N,NF]
    const float* __restrict__ colors,  // [N,NS,3]
    const float* __restrict__ dens,    // [N,NS]
    float* __restrict__ out_rgb,       // [N,3]
    float* __restrict__ out_depth,     // [N]
    float* __restrict__ out_op,        // [N]
    float* __restrict__ out_fp,        // [N,NS,3]
    int nrays)
{
    const int L   = threadIdx.x & 31;
    const int w   = threadIdx.x >> 5;
    const int ray = blockIdx.x * RPB + w;
    if (ray >= nrays) return;          // warp-uniform exit; no block barriers used

    __shared__ float2 sh_cc[RPB][64];   // (cdf[i], ct[i])
    __shared__ int    sh_mk[RPB][160];  // boundary-rank histogram
    __shared__ float  sh_t [RPB][192];  // merged sorted t
    __shared__ float2 sh_tw[RPB][192];  // (t, weight)

    float2* cc  = sh_cc[w];
    int*    mk  = sh_mk[w];
    float*  st  = sh_t[w];
    float2* stw = sh_tw[w];

    // ---- A: global loads (coalesced / vectorized) ----
    const float4 u4 = ((const float4*)(uu_in + (size_t)ray * NF))[L];
    float v0 = u4.x, v1 = u4.y, v2 = u4.z, v3 = u4.w;   // elements 4L..4L+3

    const float2 cw2 = ((const float2*)(cw + (size_t)ray * NC))[L];
    const float2 ct2 = ((const float2*)(ct + (size_t)ray * NC))[L];

    const float ox = ro[3 * ray + 0], oy = ro[3 * ray + 1], oz = ro[3 * ray + 2];
    const float dx = rd[3 * ray + 0], dy = rd[3 * ray + 1], dz = rd[3 * ray + 2];
    const float dnorm = sqrtf(dx * dx + dy * dy + dz * dz);

    // ---- B: cdf build (pair-per-lane warp scan); boundaries stay in regs ----
    float cdf_b1, cdf_b2;               // cdf[2L+1], cdf[2L+2]
    {
        const float a  = cw2.x + 1e-5f;
        const float b  = cw2.y + 1e-5f;
        const float ps = a + b;
        float inc = ps;
        #pragma unroll
        for (int off = 1; off < 32; off <<= 1) {
            float n = __shfl_up_sync(FULLM, inc, off);
            if (L >= off) inc += n;
        }
        const float total = __shfl_sync(FULLM, inc, 31);
        const float invt  = 1.f / total;
        const float excl  = inc - ps;
        const float cdf_e = excl * invt;          // cdf[2L]
        cdf_b1 = (excl + a)  * invt;              // cdf[2L+1]
        cdf_b2 = (excl + ps) * invt;              // cdf[2L+2]
        *(float4*)(cc + 2 * L) = make_float4(cdf_e, ct2.x, cdf_b1, ct2.y);
        *(int4*)(mk + 4 * L) = make_int4(0, 0, 0, 0);
        if (L < 8) *(int4*)(mk + 128 + 4 * L) = make_int4(0, 0, 0, 0);
    }

    // ---- C: bitonic sort of 128 u, 4 elements/thread (e = 4L+i) ----
    #pragma unroll
    for (int k = 2; k <= 128; k <<= 1) {
        #pragma unroll
        for (int j = k >> 1; j >= 4; j >>= 1) {
            const bool up = ((L & (k >> 2)) == 0);   // k>=8 here
            const bool lw = ((L & (j >> 2)) == 0);
            const bool km = (up == lw);
            float w0 = __shfl_xor_sync(FULLM, v0, j >> 2);
            float w1 = __shfl_xor_sync(FULLM, v1, j >> 2);
            float w2 = __shfl_xor_sync(FULLM, v2, j >> 2);
            float w3 = __shfl_xor_sync(FULLM, v3, j >> 2);
            v0 = km ? fminf(v0, w0) : fmaxf(v0, w0);
            v1 = km ? fminf(v1, w1) : fmaxf(v1, w1);
            v2 = km ? fminf(v2, w2) : fmaxf(v2, w2);
            v3 = km ? fminf(v3, w3) : fmaxf(v3, w3);
        }
        if (k >= 4) {  // j = 2 : pairs (v0,v2), (v1,v3)
            const bool up = (k == 4) ? ((L & 1) == 0) : ((L & (k >> 2)) == 0);
            CEPAIR(v0, v2, up); CEPAIR(v1, v3, up);
        }
        // j = 1 : pairs (v0,v1), (v2,v3)
        if (k == 2) {
            CEPAIR(v0, v1, true);  CEPAIR(v2, v3, false);
        } else {
            const bool up = (k == 4) ? ((L & 1) == 0) : ((L & (k >> 2)) == 0);
            CEPAIR(v0, v1, up);    CEPAIR(v2, v3, up);
        }
    }
    __syncwarp();

    // ---- D1: boundary ranks via REGISTER search; histogram + coarse scatter ----
    {
        const float m = v3;  // lane max of sorted quad; ascending across lanes
        auto rank128r = [&](float c) -> int {
            float pv; int r = 0;
            pv = __shfl_sync(FULLM, m, 15);     if (pv < c) r = 16;
            pv = __shfl_sync(FULLM, m, r + 7);  if (pv < c) r += 8;
            pv = __shfl_sync(FULLM, m, r + 3);  if (pv < c) r += 4;
            pv = __shfl_sync(FULLM, m, r + 1);  if (pv < c) r += 2;
            pv = __shfl_sync(FULLM, m, r);      if (pv < c) r += 1;
            pv = __shfl_sync(FULLM, m, 31);     if (r == 31 && pv < c) r = 32;
            const int rl = (r < 32) ? r : 31;
            const float a0 = __shfl_sync(FULLM, v0, rl);
            const float a1 = __shfl_sync(FULLM, v1, rl);
            const float a2 = __shfl_sync(FULLM, v2, rl);
            int rank = 4 * r;                   // r==32 -> 128
            if (r < 32) rank += (a0 < c) + (a1 < c) + (a2 < c);
            return rank;
        };
        const int s1 = rank128r(cdf_b1);
        const int s2 = rank128r(cdf_b2);
        atomicAdd(&mk[s1], 1);
        atomicAdd(&mk[s2], 1);
        int r0 = __shfl_up_sync(FULLM, s2, 1);
        if (L == 0) r0 = 0;
        st[2 * L + r0]     = ct2.x;
        st[2 * L + 1 + s1] = ct2.y;
    }
    __syncwarp();

    // ---- D2: lo via prefix of histogram; interpolate + scatter fine ----
    {
        const int4 m4 = *(const int4*)(mk + 4 * L);
        const int c0 = m4.x;
        const int c1 = c0 + m4.y;
        const int c2 = c1 + m4.z;
        const int c3 = c2 + m4.w;
        int inc = c3;
        #pragma unroll
        for (int off = 1; off < 32; off <<= 1) {
            int n = __shfl_up_sync(FULLM, inc, off);
            if (L >= off) inc += n;
        }
        const int exc = inc - c3;
        const int lov[4] = {1 + exc + c0, 1 + exc + c1, 1 + exc + c2, 1 + exc + c3};
        const float va[4] = {v0, v1, v2, v3};
        #pragma unroll
        for (int i = 0; i < 4; i++) {
            const int   lo = lov[i];
            const float uu = va[i];
            const int below = min(lo - 1, NC - 1);
            const int above = min(lo,     NC - 1);
            const float2 ccb = cc[below];
            const float2 cca = cc[above];
            float denom = cca.x - ccb.x;
            if (denom < 1e-5f) denom = 1.f;
            const float tt = (uu - ccb.x) / denom;
            const float fv = ccb.y + tt * (cca.y - ccb.y);
            st[4 * L + i + min(lo, NC)] = fv;
        }
    }
    __syncwarp();

    // ---- F: alpha + transmittance (thread owns samples 6L..6L+5) ----
    float dep = 0.f, op = 0.f;
    {
        const float2 tA = *(const float2*)(st + 6 * L);
        const float2 tB = *(const float2*)(st + 6 * L + 2);
        const float2 tC = *(const float2*)(st + 6 * L + 4);
        const float tb[6] = {tA.x, tA.y, tB.x, tB.y, tC.x, tC.y};
        // st[6L+6] == next lane's tA.x (lane 31's value unused: 1e10 branch)
        const float t6 = __shfl_down_sync(FULLM, tA.x, 1);

        const float* dvp = dens + (size_t)ray * NS + 6 * L;
        const float2 dva = *(const float2*)(dvp + 0);
        const float2 dvb = *(const float2*)(dvp + 2);
        const float2 dvc = *(const float2*)(dvp + 4);
        const float dvv[6] = {dva.x, dva.y, dvb.x, dvb.y, dvc.x, dvc.y};

        float alpha[6];
        float run = 1.f;
        #pragma unroll
        for (int i = 0; i < 6; i++) {
            float dist;
            if (i < 5)          dist = tb[i + 1] - tb[i];
            else if (L == 31)   dist = 1e10f;
            else                dist = t6 - tb[5];
            dist *= dnorm;
            alpha[i] = 1.f - __expf(-dvv[i] * dist);
            run *= (1.f - alpha[i] + 1e-10f);
        }
        float inc = run;
        #pragma unroll
        for (int off = 1; off < 32; off <<= 1) {
            float n = __shfl_up_sync(FULLM, inc, off);
            if (L >= off) inc *= n;
        }
        float wex = __shfl_up_sync(FULLM, inc, 1);
        if (L == 0) wex = 1.f;

        float run2 = wex;                 // running transmittance
        #pragma unroll
        for (int i = 0; i < 6; i++) {
            const float wt = alpha[i] * run2;
            stw[6 * L + i] = make_float2(tb[i], wt);
            dep += wt * tb[i];
            op  += wt;
            run2 *= (1.f - alpha[i] + 1e-10f);
        }
    }
    __syncwarp();

    // ---- G: float4 fp stores + rgb accumulation (contiguous stw reads) ----
    float A0 = 0.f, A1 = 0.f, A2 = 0.f;
    const int rB = L % 3;
    {
        const float oR0 = (rB == 0) ? ox : ((rB == 1) ? oy : oz);
        const float oR1 = (rB == 0) ? oy : ((rB == 1) ? oz : ox);
        const float oR2 = (rB == 0) ? oz : ((rB == 1) ? ox : oy);
        const float dR0 = (rB == 0) ? dx : ((rB == 1) ? dy : dz);
        const float dR1 = (rB == 0) ? dy : ((rB == 1) ? dz : dx);
        const float dR2 = (rB == 0) ? dz : ((rB == 1) ? dx : dy);
        float* fpb = out_fp + (size_t)ray * (NS * 3);
        const float4* c4 = (const float4*)(colors + (size_t)ray * (NS * 3));

        #pragma unroll
        for (int h = 0; h < 4; h++) {
            const float4 cvi = __ldg(&c4[32 * h + L]);
            const int e0  = 128 * h + 4 * L;
            const int sa  = e0 / 3;
            const int r0  = e0 - 3 * sa;           // e0 % 3
            const float2 twa = stw[sa];
            const float2 twb = stw[sa + 1];
            // float j uses sample sa+1 iff r0 + j >= 3
            const float t0 = twa.x;
            const float w0 = twa.y;
            const float t1 = (r0 == 2) ? twb.x : twa.x;
            const float w1 = (r0 == 2) ? twb.y : twa.y;
            const float t2 = (r0 >= 1) ? twb.x : twa.x;
            const float w2 = (r0 >= 1) ? twb.y : twa.y;
            const float t3 = twb.x;
            const float w3 = twb.y;
            // channel slot q_j = (2h + j) % 3 (compile-time)
            const int q0 = (2 * h + 0) % 3, q1 = (2 * h + 1) % 3;
            const int q2 = (2 * h + 2) % 3, q3 = (2 * h + 3) % 3;
            const float oA = (q0 == 0) ? oR0 : ((q0 == 1) ? oR1 : oR2);
            const float dA = (q0 == 0) ? dR0 : ((q0 == 1) ? dR1 : dR2);
            const float oB = (q1 == 0) ? oR0 : ((q1 == 1) ? oR1 : oR2);
            const float dB = (q1 == 0) ? dR0 : ((q1 == 1) ? dR1 : dR2);
            const float oC = (q2 == 0) ? oR0 : ((q2 == 1) ? oR1 : oR2);
            const float dC = (q2 == 0) ? dR0 : ((q2 == 1) ? dR1 : dR2);
            const float oD = (q3 == 0) ? oR0 : ((q3 == 1) ? oR1 : oR2);
            const float dD = (q3 == 0) ? dR0 : ((q3 == 1) ? dR1 : dR2);
            *(float4*)(fpb + e0) = make_float4(oA + dA * t0, oB + dB * t1,
                                               oC + dC * t2, oD + dD * t3);
            const float g0 = w0 * cvi.x, g1 = w1 * cvi.y;
            const float g2 = w2 * cvi.z, g3 = w3 * cvi.w;
            if (q0 == 0) A0 += g0; else if (q0 == 1) A1 += g0; else A2 += g0;
            if (q1 == 0) A0 += g1; else if (q1 == 1) A1 += g1; else A2 += g1;
            if (q2 == 0) A0 += g2; else if (q2 == 1) A1 += g2; else A2 += g2;
            if (q3 == 0) A0 += g3; else if (q3 == 1) A1 += g3; else A2 += g3;
        }

        // tail: elements 512 + 2L, 512 + 2L + 1 (float2)
        {
            const float2* c2p = (const float2*)(colors + (size_t)ray * (NS * 3) + 512);
            const float2 cvi = __ldg(&c2p[L]);
            const int e0 = 512 + 2 * L;
            const int s0 = e0 / 3;
            const int s1t = (e0 + 1) / 3;
            const float2 tw0 = stw[s0];
            const float2 tw1 = stw[s1t];
            const int qt0 = (2 + rB) % 3;
            const int qt1 = rB;
            const float o0 = (qt0 == 0) ? oR0 : ((qt0 == 1) ? oR1 : oR2);
            const float d0 = (qt0 == 0) ? dR0 : ((qt0 == 1) ? dR1 : dR2);
            const float o1 = (qt1 == 0) ? oR0 : ((qt1 == 1) ? oR1 : oR2);
            const float d1 = (qt1 == 0) ? dR0 : ((qt1 == 1) ? dR1 : dR2);
            *(float2*)(fpb + e0) = make_float2(o0 + d0 * tw0.x, o1 + d1 * tw1.x);
            const float g0 = tw0.y * cvi.x;
            const float g1 = tw1.y * cvi.y;
            if (qt0 == 0) A0 += g0; else if (qt0 == 1) A1 += g0; else A2 += g0;
            if (qt1 == 0) A0 += g1; else if (qt1 == 1) A1 += g1; else A2 += g1;
        }
    }

    // ---- H: final reductions (single warp, no shared) ----
    {
        // channel c lives in A[(c - rB) mod 3] == A[(c + 2L) % 3]
        const int i0 = (2 * L) % 3, i1 = (2 * L + 1) % 3, i2 = (2 * L + 2) % 3;
        float rC = (i0 == 0) ? A0 : ((i0 == 1) ? A1 : A2);
        float gC = (i1 == 0) ? A0 : ((i1 == 1) ? A1 : A2);
        float bC = (i2 == 0) ? A0 : ((i2 == 1) ? A1 : A2);
        #pragma unroll
        for (int off = 16; off; off >>= 1) {
            rC  += __shfl_xor_sync(FULLM, rC,  off);
            gC  += __shfl_xor_sync(FULLM, gC,  off);
            bC  += __shfl_xor_sync(FULLM, bC,  off);
            dep += __shfl_xor_sync(FULLM, dep, off);
            op  += __shfl_xor_sync(FULLM, op,  off);
        }
        if (L == 0) {
            out_rgb[3 * ray + 0] = rC;
            out_rgb[3 * ray + 1] = gC;
            out_rgb[3 * ray + 2] = bC;
            out_depth[ray] = dep;
            out_op[ray]    = op;
        }
    }
}

extern "C" void kernel_launch(void* const* d_in, const int* in_sizes, int n_in,
                              void* d_out, int out_size)
{
    const float* ro     = (const float*)d_in[0];
    const float* rd     = (const float*)d_in[1];
    const float* cw     = (const float*)d_in[2];
    const float* ct     = (const float*)d_in[3];
    const float* u      = (const float*)d_in[4];
    const float* colors = (const float*)d_in[5];
    const float* dens   = (const float*)d_in[6];

    const int N = in_sizes[0] / 3;

    float* out       = (float*)d_out;
    float* out_rgb   = out;                 // [N,3]
    float* out_depth = out + (size_t)N * 3; // [N]
    float* out_op    = out_depth + N;       // [N]
    float* out_fp    = out_op + N;          // [N,NS,3]

    const int blocks = (N + RPB - 1) / RPB;
    gridnerf_kernel<<<blocks, 32 * RPB>>>(ro, rd, cw, ct, u, colors, dens,
                                          out_rgb, out_depth, out_op, out_fp, N);
}